// round 17
// baseline (speedup 1.0000x reference)
#include <cuda_runtime.h>
#include <cuda_bf16.h>
#include <math.h>
#include <stdint.h>

#define DI    1024
#define DH    2048
#define S_LEN 4096
#define BATCH 4
#define M_TOT (BATCH * S_LEN)   // 16384
#define N1    (3 * DH)          // 6144

#define OUT_ELEMS ((size_t)M_TOT * DI)
#define NH_OFF    OUT_ELEMS
#define NLH_OFF   (OUT_ELEMS + (size_t)BATCH * DH)

#define CHUNK 64
#define NCH   (S_LEN / CHUNK)   // 64
#define BD    (BATCH * DH)      // 8192

// ---------------- static scratch ------------------------------------------
__device__ float         g_C[(size_t)M_TOT * DH];
__device__ float         g_V[(size_t)M_TOT * DH];
__device__ __nv_bfloat16 g_Xhi[(size_t)M_TOT * DI];
__device__ __nv_bfloat16 g_Xlo[(size_t)M_TOT * DI];
__device__ __nv_bfloat16 g_W1Thi[(size_t)N1 * DI];   // [N1][DI]
__device__ __nv_bfloat16 g_W1Tlo[(size_t)N1 * DI];
__device__ __nv_bfloat16 g_Hhi[(size_t)M_TOT * DH];
__device__ __nv_bfloat16 g_Hlo[(size_t)M_TOT * DH];
__device__ __nv_bfloat16 g_W2Thi[(size_t)DI * DH];   // [DI][DH]
__device__ __nv_bfloat16 g_W2Tlo[(size_t)DI * DH];
// scan scratch
__device__ float g_Ak [(size_t)NCH * BD];
__device__ float g_Bk [(size_t)NCH * BD];
__device__ float g_Hin[(size_t)NCH * BD];

// ---------------- math helpers --------------------------------------------
__device__ __forceinline__ float softplusf(float z) {
    return z > 15.f ? z : log1pf(__expf(z));
}
__device__ __forceinline__ float sigmoidf(float z) {
    return 1.f / (1.f + __expf(-z));
}
__device__ __forceinline__ float g_fn(float x) {
    return x >= 0.f ? x + 0.5f : sigmoidf(x);
}
__device__ __forceinline__ void splitf(float a, __nv_bfloat16& hi, __nv_bfloat16& lo) {
    __nv_bfloat16 h = __float2bfloat16(a);
    hi = h;
    lo = __float2bfloat16(a - __bfloat162float(h));
}

// ---------------- PTX helpers ----------------------------------------------
__device__ __forceinline__ uint32_t smem_u32(const void* p) {
    uint32_t a;
    asm("{ .reg .u64 t; cvta.to.shared.u64 t, %1; cvt.u32.u64 %0, t; }"
        : "=r"(a) : "l"(p));
    return a;
}
#define CP16(dst, src) \
    asm volatile("cp.async.cg.shared.global [%0], [%1], 16;" \
                 :: "r"(dst), "l"(src))
#define CP_COMMIT() asm volatile("cp.async.commit_group;" ::: "memory")
#define CP_WAIT0()  asm volatile("cp.async.wait_group 0;" ::: "memory")

#define LDSM4(r, addr) \
    asm volatile("ldmatrix.sync.aligned.m8n8.x4.shared.b16 {%0,%1,%2,%3}, [%4];" \
        : "=r"((r)[0]), "=r"((r)[1]), "=r"((r)[2]), "=r"((r)[3]) : "r"(addr))

#define MMA16816(d, a, b0v, b1v) \
    asm volatile("mma.sync.aligned.m16n8k16.row.col.f32.bf16.bf16.f32 " \
        "{%0,%1,%2,%3}, {%4,%5,%6,%7}, {%8,%9}, {%0,%1,%2,%3};" \
        : "+f"((d)[0]), "+f"((d)[1]), "+f"((d)[2]), "+f"((d)[3]) \
        : "r"((a)[0]), "r"((a)[1]), "r"((a)[2]), "r"((a)[3]), \
          "r"(b0v), "r"(b1v))

__device__ __forceinline__ uint32_t swz128(uint32_t o) { return o ^ ((o >> 3) & 0x70); }

// ---------------------------------------------------------------------------
// split X -> bf16 hi/lo
// ---------------------------------------------------------------------------
__global__ __launch_bounds__(256) void split_x_kernel(const float* __restrict__ X) {
    size_t i = (size_t)blockIdx.x * 256 + threadIdx.x;
    float4 v = reinterpret_cast<const float4*>(X)[i];
    __nv_bfloat16 h[4], l[4];
    splitf(v.x, h[0], l[0]); splitf(v.y, h[1], l[1]);
    splitf(v.z, h[2], l[2]); splitf(v.w, h[3], l[3]);
    *reinterpret_cast<uint2*>(&g_Xhi[i * 4]) = *reinterpret_cast<uint2*>(h);
    *reinterpret_cast<uint2*>(&g_Xlo[i * 4]) = *reinterpret_cast<uint2*>(l);
}

// ---------------------------------------------------------------------------
// transpose + split  W[R][C] -> T[C][R] bf16 hi/lo
// ---------------------------------------------------------------------------
__device__ __forceinline__ void tsplit_body(const float* __restrict__ W,
                                            __nv_bfloat16* __restrict__ Thi,
                                            __nv_bfloat16* __restrict__ Tlo,
                                            int R, int C) {
    __shared__ float t[32][33];
    int tx = threadIdx.x, ty = threadIdx.y;
    int c0 = blockIdx.x * 32, r0 = blockIdx.y * 32;
    #pragma unroll
    for (int j = 0; j < 32; j += 8)
        t[ty + j][tx] = W[(size_t)(r0 + ty + j) * C + c0 + tx];
    __syncthreads();
    #pragma unroll
    for (int j = 0; j < 32; j += 8) {
        float a = t[tx][ty + j];
        __nv_bfloat16 h, l; splitf(a, h, l);
        size_t o = (size_t)(c0 + ty + j) * R + r0 + tx;
        Thi[o] = h; Tlo[o] = l;
    }
}
__global__ __launch_bounds__(256) void tsplit_w1_kernel(const float* __restrict__ W1) {
    tsplit_body(W1, g_W1Thi, g_W1Tlo, DI, N1);
}
__global__ __launch_bounds__(256) void tsplit_w2_kernel(const float* __restrict__ W2) {
    tsplit_body(W2, g_W2Thi, g_W2Tlo, DH, DI);
}

// ---------------------------------------------------------------------------
// K1: proj = x@W1 (+b1, gate math, chunk-scan fused) -> g_C, g_V, g_Ak, g_Bk
// block 256m x 96n, 8 warps, warp tile 64m x 48n, BK=64, 2-stage, 1 CTA/SM
// stage: Ahi 32K | Alo 32K | Bhi 12K | Blo 12K = 90112 ; x2 = 180224
// ---------------------------------------------------------------------------
#define G1_STAGE 90112
#define G1_SMEM  (2 * G1_STAGE)

__global__ __launch_bounds__(256, 1) void gemm1_mma_kernel(const float* __restrict__ b1) {
    extern __shared__ char sm[];
    const uint32_t sb = smem_u32(sm);
    const int tid = threadIdx.x, lane = tid & 31, wid = tid >> 5;
    const int wm = wid >> 1, wn = wid & 1;           // wm 0..3 (64 rows), wn 0..1 (48 cols)
    const int m0 = blockIdx.y * 256, cb0 = blockIdx.x * 32;

    float acc[4][6][4];
    #pragma unroll
    for (int i = 0; i < 4; i++)
        #pragma unroll
        for (int j = 0; j < 6; j++)
            #pragma unroll
            for (int k = 0; k < 4; k++) acc[i][j][k] = 0.f;

    #define G1_PREFETCH(s, kt) do {                                            \
        uint32_t A0_ = sb + (s) * G1_STAGE;                                    \
        uint32_t L0_ = A0_ + 32768, B0_ = A0_ + 65536, B1_ = A0_ + 77824;      \
        _Pragma("unroll")                                                      \
        for (int i = 0; i < 8; i++) {                                          \
            int idx = tid + i * 256;                                           \
            int r = idx >> 3, c = idx & 7;                                     \
            uint32_t d = swz128((uint32_t)(r * 128 + c * 16));                 \
            CP16(A0_ + d, g_Xhi + (size_t)(m0 + r) * DI + (kt) + c * 8);       \
            CP16(L0_ + d, g_Xlo + (size_t)(m0 + r) * DI + (kt) + c * 8);       \
        }                                                                      \
        _Pragma("unroll")                                                      \
        for (int i = 0; i < 3; i++) {                                          \
            int idx = tid + i * 256;                                           \
            int r = idx >> 3, c = idx & 7;                                     \
            int gate = r >> 5, chl = r & 31;                                   \
            size_t row = (size_t)(gate * DH + cb0 + chl) * DI + (kt) + c * 8;  \
            uint32_t d = swz128((uint32_t)(r * 128 + c * 16));                 \
            CP16(B0_ + d, g_W1Thi + row); CP16(B1_ + d, g_W1Tlo + row);        \
        }                                                                      \
    } while (0)

    G1_PREFETCH(0, 0);
    CP_COMMIT();

    const int arow  = wm * 64 + (lane & 15);
    const int browb = wn * 48 + ((lane >> 4) << 3) + (lane & 7);

    for (int ck = 0; ck < 16; ck++) {
        CP_WAIT0();
        __syncthreads();
        if (ck + 1 < 16) {
            G1_PREFETCH((ck + 1) & 1, (ck + 1) * 64);
            CP_COMMIT();
        }
        const uint32_t A0 = sb + (ck & 1) * G1_STAGE;
        const uint32_t L0 = A0 + 32768, B0 = A0 + 65536, B1 = A0 + 77824;
        #pragma unroll
        for (int kk = 0; kk < 64; kk += 16) {
            const uint32_t acol = (uint32_t)(kk + (lane >> 4) * 8) * 2;
            const uint32_t bcol = (uint32_t)(kk + ((lane >> 3) & 1) * 8) * 2;
            uint32_t ahi[4][4], alo[4][4], bhi[3][4], blo[3][4];
            #pragma unroll
            for (int im = 0; im < 4; im++) {
                LDSM4(ahi[im], A0 + swz128((uint32_t)((arow + im * 16) * 128) + acol));
                LDSM4(alo[im], L0 + swz128((uint32_t)((arow + im * 16) * 128) + acol));
            }
            #pragma unroll
            for (int j = 0; j < 3; j++) {
                LDSM4(bhi[j], B0 + swz128((uint32_t)((browb + j * 16) * 128) + bcol));
                LDSM4(blo[j], B1 + swz128((uint32_t)((browb + j * 16) * 128) + bcol));
            }
            #pragma unroll
            for (int tm = 0; tm < 4; tm++)
                #pragma unroll
                for (int tn = 0; tn < 6; tn++)
                    MMA16816(acc[tm][tn], ahi[tm],
                             bhi[tn >> 1][(tn & 1) * 2], bhi[tn >> 1][(tn & 1) * 2 + 1]);
            #pragma unroll
            for (int tm = 0; tm < 4; tm++)
                #pragma unroll
                for (int tn = 0; tn < 6; tn++)
                    MMA16816(acc[tm][tn], ahi[tm],
                             blo[tn >> 1][(tn & 1) * 2], blo[tn >> 1][(tn & 1) * 2 + 1]);
            #pragma unroll
            for (int tm = 0; tm < 4; tm++)
                #pragma unroll
                for (int tn = 0; tn < 6; tn++)
                    MMA16816(acc[tm][tn], alo[tm],
                             bhi[tn >> 1][(tn & 1) * 2], bhi[tn >> 1][(tn & 1) * 2 + 1]);
        }
    }
    __syncthreads();

    // ---- epilogue: acc -> proj smem -> gate math -> g_C/g_V + chunk scan ----
    float* proj = reinterpret_cast<float*>(sm);     // [256][100] = 102400 B
    #pragma unroll
    for (int tm = 0; tm < 4; tm++)
        #pragma unroll
        for (int tn = 0; tn < 6; tn++) {
            int row = wm * 64 + tm * 16 + (lane >> 2);
            int col = wn * 48 + tn * 8 + 2 * (lane & 3);
            *reinterpret_cast<float2*>(&proj[row * 100 + col]) =
                make_float2(acc[tm][tn][0], acc[tm][tn][1]);
            *reinterpret_cast<float2*>(&proj[(row + 8) * 100 + col]) =
                make_float2(acc[tm][tn][2], acc[tm][tn][3]);
        }
    __syncthreads();

    const int ch = tid & 31;
    const int seg = tid >> 5;                        // 8 segments of 32 rows
    const float bh = __ldg(&b1[cb0 + ch]);
    const float bf = __ldg(&b1[DH + cb0 + ch]);
    const float bi = __ldg(&b1[2 * DH + cb0 + ch]);
    float Aa = 1.f, Bb = 0.f;
    #pragma unroll
    for (int j = 0; j < 32; j++) {
        int row = seg * 32 + j;                      // sequential in time
        float hid = proj[row * 100 + ch] + bh;
        float fg  = proj[row * 100 + 32 + ch] + bf;
        float ig  = proj[row * 100 + 64 + ch] + bi;
        float diff = softplusf(-fg) - softplusf(-ig);
        float c = sigmoidf(-diff);
        float v = sigmoidf(diff) * g_fn(hid);
        size_t o = (size_t)(m0 + row) * DH + cb0 + ch;
        g_C[o] = c;
        g_V[o] = v;
        Aa *= c;
        Bb = fmaf(c, Bb, v);
    }
    float* pA = reinterpret_cast<float*>(sm + 102400);   // [8][32]
    float* pB = pA + 256;
    pA[seg * 32 + ch] = Aa;
    pB[seg * 32 + ch] = Bb;
    __syncthreads();
    if (tid < 128) {
        int cl = tid >> 5, c2 = tid & 31;            // 4 chunks x 32 channels
        float A0v = pA[(2 * cl) * 32 + c2],     B0v = pB[(2 * cl) * 32 + c2];
        float A1v = pA[(2 * cl + 1) * 32 + c2], B1v = pB[(2 * cl + 1) * 32 + c2];
        float A = A1v * A0v;
        float Bv = fmaf(A1v, B0v, B1v);
        int b     = m0 / S_LEN;
        int chunk = (m0 % S_LEN) / CHUNK + cl;
        size_t t = (size_t)chunk * BD + (size_t)b * DH + cb0 + c2;
        g_Ak[t] = A;
        g_Bk[t] = Bv;
    }
    #undef G1_PREFETCH
}

// ---------------------------------------------------------------------------
// scan carry + emit
// ---------------------------------------------------------------------------
__global__ __launch_bounds__(256) void scan_carry_kernel(
    const float* __restrict__ initH, float* __restrict__ out)
{
    int bd = blockIdx.x * 256 + threadIdx.x;         // b*DH + d
    int d = bd & (DH - 1);
    float h = g_fn(initH[d]);
    #pragma unroll 8
    for (int ch = 0; ch < NCH; ch++) {
        int t = ch * BD + bd;
        g_Hin[t] = h;
        h = fmaf(g_Ak[t], h, g_Bk[t]);
    }
    out[NH_OFF  + bd] = h;
    out[NLH_OFF + bd] = logf(h);
}

__global__ __launch_bounds__(256) void scan_emit_kernel() {
    int t = blockIdx.x * 256 + threadIdx.x;
    int bd = t & (BD - 1);
    int chunk = t >> 13;
    int b = bd >> 11, d = bd & (DH - 1);
    size_t base = ((size_t)b * S_LEN + (size_t)chunk * CHUNK) * DH + d;
    float h = g_Hin[t];
    #pragma unroll 8
    for (int s = 0; s < CHUNK; s++) {
        size_t idx = base + (size_t)s * DH;
        h = fmaf(g_C[idx], h, g_V[idx]);
        __nv_bfloat16 hh, hl; splitf(h, hh, hl);
        g_Hhi[idx] = hh; g_Hlo[idx] = hl;
    }
}

// ---------------------------------------------------------------------------
// K3: out = h@W2 + b2
// block 256m x 128n, 8 warps, warp tile 64m x 64n, BK=64, 2-stage, 1 CTA/SM
// stage: Ahi 32K | Alo 32K | Bhi 16K | Blo 16K = 98304 ; x2 = 196608
// ---------------------------------------------------------------------------
#define G2_STAGE 98304
#define G2_SMEM  (2 * G2_STAGE)

__global__ __launch_bounds__(256, 1) void gemm2_mma_kernel(
    const float* __restrict__ b2, float* __restrict__ out)
{
    extern __shared__ char sm[];
    const uint32_t sb = smem_u32(sm);
    const int tid = threadIdx.x, lane = tid & 31, wid = tid >> 5;
    const int wm = wid >> 1, wn = wid & 1;           // wm 0..3 (64 rows), wn 0..1 (64 cols)
    const int m0 = blockIdx.y * 256, n0 = blockIdx.x * 128;

    float acc[4][8][4];
    #pragma unroll
    for (int i = 0; i < 4; i++)
        #pragma unroll
        for (int j = 0; j < 8; j++)
            #pragma unroll
            for (int k = 0; k < 4; k++) acc[i][j][k] = 0.f;

    #define G2_PREFETCH(s, kt) do {                                            \
        uint32_t A0_ = sb + (s) * G2_STAGE;                                    \
        uint32_t L0_ = A0_ + 32768, B0_ = A0_ + 65536, B1_ = A0_ + 81920;      \
        _Pragma("unroll")                                                      \
        for (int i = 0; i < 8; i++) {                                          \
            int idx = tid + i * 256;                                           \
            int r = idx >> 3, c = idx & 7;                                     \
            uint32_t d = swz128((uint32_t)(r * 128 + c * 16));                 \
            CP16(A0_ + d, g_Hhi + (size_t)(m0 + r) * DH + (kt) + c * 8);       \
            CP16(L0_ + d, g_Hlo + (size_t)(m0 + r) * DH + (kt) + c * 8);       \
        }                                                                      \
        _Pragma("unroll")                                                      \
        for (int i = 0; i < 4; i++) {                                          \
            int idx = tid + i * 256;                                           \
            int r = idx >> 3, c = idx & 7;                                     \
            uint32_t d = swz128((uint32_t)(r * 128 + c * 16));                 \
            CP16(B0_ + d, g_W2Thi + (size_t)(n0 + r) * DH + (kt) + c * 8);     \
            CP16(B1_ + d, g_W2Tlo + (size_t)(n0 + r) * DH + (kt) + c * 8);     \
        }                                                                      \
    } while (0)

    G2_PREFETCH(0, 0);
    CP_COMMIT();

    const int arow  = wm * 64 + (lane & 15);
    const int browb = wn * 64 + ((lane >> 4) << 3) + (lane & 7);

    for (int ck = 0; ck < 32; ck++) {
        CP_WAIT0();
        __syncthreads();
        if (ck + 1 < 32) {
            G2_PREFETCH((ck + 1) & 1, (ck + 1) * 64);
            CP_COMMIT();
        }
        const uint32_t A0 = sb + (ck & 1) * G2_STAGE;
        const uint32_t L0 = A0 + 32768, B0 = A0 + 65536, B1 = A0 + 81920;
        #pragma unroll
        for (int kk = 0; kk < 64; kk += 16) {
            const uint32_t acol = (uint32_t)(kk + (lane >> 4) * 8) * 2;
            const uint32_t bcol = (uint32_t)(kk + ((lane >> 3) & 1) * 8) * 2;
            uint32_t ahi[4][4], alo[4][4], bhi[4][4], blo[4][4];
            #pragma unroll
            for (int im = 0; im < 4; im++) {
                LDSM4(ahi[im], A0 + swz128((uint32_t)((arow + im * 16) * 128) + acol));
                LDSM4(alo[im], L0 + swz128((uint32_t)((arow + im * 16) * 128) + acol));
            }
            #pragma unroll
            for (int j = 0; j < 4; j++) {
                LDSM4(bhi[j], B0 + swz128((uint32_t)((browb + j * 16) * 128) + bcol));
                LDSM4(blo[j], B1 + swz128((uint32_t)((browb + j * 16) * 128) + bcol));
            }
            #pragma unroll
            for (int tm = 0; tm < 4; tm++)
                #pragma unroll
                for (int tn = 0; tn < 8; tn++)
                    MMA16816(acc[tm][tn], ahi[tm],
                             bhi[tn >> 1][(tn & 1) * 2], bhi[tn >> 1][(tn & 1) * 2 + 1]);
            #pragma unroll
            for (int tm = 0; tm < 4; tm++)
                #pragma unroll
                for (int tn = 0; tn < 8; tn++)
                    MMA16816(acc[tm][tn], ahi[tm],
                             blo[tn >> 1][(tn & 1) * 2], blo[tn >> 1][(tn & 1) * 2 + 1]);
            #pragma unroll
            for (int tm = 0; tm < 4; tm++)
                #pragma unroll
                for (int tn = 0; tn < 8; tn++)
                    MMA16816(acc[tm][tn], alo[tm],
                             bhi[tn >> 1][(tn & 1) * 2], bhi[tn >> 1][(tn & 1) * 2 + 1]);
        }
    }

    // ---- epilogue: + b2, direct stores ----
    #pragma unroll
    for (int tm = 0; tm < 4; tm++)
        #pragma unroll
        for (int tn = 0; tn < 8; tn++) {
            int row = m0 + wm * 64 + tm * 16 + (lane >> 2);
            int col = n0 + wn * 64 + tn * 8 + 2 * (lane & 3);
            float bb0 = __ldg(&b2[col]), bb1 = __ldg(&b2[col + 1]);
            *reinterpret_cast<float2*>(&out[(size_t)row * DI + col]) =
                make_float2(acc[tm][tn][0] + bb0, acc[tm][tn][1] + bb1);
            *reinterpret_cast<float2*>(&out[(size_t)(row + 8) * DI + col]) =
                make_float2(acc[tm][tn][2] + bb0, acc[tm][tn][3] + bb1);
        }
    #undef G2_PREFETCH
}

// ---------------------------------------------------------------------------
extern "C" void kernel_launch(void* const* d_in, const int* in_sizes, int n_in,
                              void* d_out, int out_size)
{
    const float* x     = (const float*)d_in[0];
    const float* W1    = (const float*)d_in[1];
    const float* b1    = (const float*)d_in[2];
    const float* W2    = (const float*)d_in[3];
    const float* b2    = (const float*)d_in[4];
    const float* initH = (const float*)d_in[5];
    float* out = (float*)d_out;

    cudaFuncSetAttribute(gemm1_mma_kernel,
                         cudaFuncAttributeMaxDynamicSharedMemorySize, G1_SMEM);
    cudaFuncSetAttribute(gemm2_mma_kernel,
                         cudaFuncAttributeMaxDynamicSharedMemorySize, G2_SMEM);

    split_x_kernel<<<(M_TOT * DI) / (4 * 256), 256>>>(x);
    tsplit_w1_kernel<<<dim3(N1 / 32, DI / 32), dim3(32, 8)>>>(W1);
    tsplit_w2_kernel<<<dim3(DI / 32, DH / 32), dim3(32, 8)>>>(W2);

    gemm1_mma_kernel<<<dim3(DH / 32, M_TOT / 256), 256, G1_SMEM>>>(b1);

    scan_carry_kernel<<<BD / 256, 256>>>(initH, out);
    scan_emit_kernel<<<(NCH * BD) / 256, 256>>>();

    gemm2_mma_kernel<<<dim3(DI / 128, M_TOT / 256), 256, G2_SMEM>>>(b2, out);
}